// round 4
// baseline (speedup 1.0000x reference)
#include <cuda_runtime.h>
#include <cuda_bf16.h>

#define NNODES 100000
#define DEG     16
#define DIM     128
#define NEG_SLOPE 0.01f

// ---------------- scratch (static device globals; no allocation) ----------------
__device__ float g_z [NNODES * DIM];   // z   = h @ W_W^T
__device__ float g_zi[NNODES * DIM];   // z_i = h @ W_U^T
__device__ float g_h [NNODES * DIM];   // layer-1 output
__device__ float g_ss[NNODES];         // s_src per node
__device__ float g_sd[NNODES];         // s_dst per node

// ---------------------------------------------------------------------------
// GEMM kernel: for a 64-row tile, computes
//   z  = h @ W_W^T   (and epilogue s_src = z@a_src, s_dst = z@a_dst)
//   zi = h @ W_U^T
// 256 threads, register tile 4x8 (TM=4, TN=8), BN = full 128 cols, BK = 16.
// ---------------------------------------------------------------------------
__global__ __launch_bounds__(256) void gat_gemm_kernel(
    const float* __restrict__ h,     // [N,128]
    const float* __restrict__ Ww,    // [128,128] row-major: Ww[j][k]
    const float* __restrict__ Wu,    // [128,128]
    const float* __restrict__ Wa,    // [257]
    float* __restrict__ z,
    float* __restrict__ zi,
    float* __restrict__ ssrc,
    float* __restrict__ sdst)
{
    __shared__ __align__(16) float hsT[DIM][64];     // 32 KB, h tile transposed
    __shared__ __align__(16) float Bs[16][DIM];      // 8 KB, W^T chunk: Bs[k][j]=W[j][k]
    __shared__ float sred[2][64][16];                // 8 KB, s reduction

    const int tid = threadIdx.x;
    const int tx  = tid & 15;        // 0..15 -> 8 output cols each
    const int ty  = tid >> 4;        // 0..15 -> 4 output rows each
    const int row0 = blockIdx.x * 64;

    // ---- load h tile into smem, transposed: hsT[k][r] = h[row0+r][k] ----
#pragma unroll
    for (int p = 0; p < 8; p++) {
        int idx = tid + p * 256;              // 0..2047
        int r   = idx >> 5;                   // 0..63
        int c4  = idx & 31;                   // 0..31  (float4 along k)
        float4 v = make_float4(0.f, 0.f, 0.f, 0.f);
        int row = row0 + r;
        if (row < NNODES) v = *(const float4*)&h[row * DIM + c4 * 4];
        hsT[c4 * 4 + 0][r] = v.x;
        hsT[c4 * 4 + 1][r] = v.y;
        hsT[c4 * 4 + 2][r] = v.z;
        hsT[c4 * 4 + 3][r] = v.w;
    }

#pragma unroll 1
    for (int w = 0; w < 2; w++) {
        const float* W = w ? Wu : Ww;
        float acc[4][8];
#pragma unroll
        for (int m = 0; m < 4; m++)
#pragma unroll
            for (int n = 0; n < 8; n++) acc[m][n] = 0.f;

        for (int kb = 0; kb < DIM; kb += 16) {
            __syncthreads();
            // load Bs[kk][j] = W[j][kb+kk]
#pragma unroll
            for (int p = 0; p < 2; p++) {
                int idx = tid + p * 256;          // 0..511
                int j   = idx >> 2;               // 0..127
                int kq  = idx & 3;                // 0..3
                float4 v = *(const float4*)&W[j * DIM + kb + kq * 4];
                Bs[kq * 4 + 0][j] = v.x;
                Bs[kq * 4 + 1][j] = v.y;
                Bs[kq * 4 + 2][j] = v.z;
                Bs[kq * 4 + 3][j] = v.w;
            }
            __syncthreads();

#pragma unroll
            for (int kk = 0; kk < 16; kk++) {
                float4 a  = *(const float4*)&hsT[kb + kk][ty * 4];
                float4 b0 = *(const float4*)&Bs[kk][tx * 8];
                float4 b1 = *(const float4*)&Bs[kk][tx * 8 + 4];
                float av[4] = {a.x, a.y, a.z, a.w};
                float bv[8] = {b0.x, b0.y, b0.z, b0.w, b1.x, b1.y, b1.z, b1.w};
#pragma unroll
                for (int m = 0; m < 4; m++)
#pragma unroll
                    for (int n = 0; n < 8; n++)
                        acc[m][n] = fmaf(av[m], bv[n], acc[m][n]);
            }
        }

        // ---- write result tile ----
        float* out = w ? zi : z;
#pragma unroll
        for (int m = 0; m < 4; m++) {
            int row = row0 + ty * 4 + m;
            if (row < NNODES) {
                *(float4*)&out[row * DIM + tx * 8]     =
                    make_float4(acc[m][0], acc[m][1], acc[m][2], acc[m][3]);
                *(float4*)&out[row * DIM + tx * 8 + 4] =
                    make_float4(acc[m][4], acc[m][5], acc[m][6], acc[m][7]);
            }
        }

        // ---- epilogue: s_src = z@a_src, s_dst = z@a_dst (only for w==0) ----
        if (w == 0) {
            float as[8], ad[8];
#pragma unroll
            for (int n = 0; n < 8; n++) {
                as[n] = Wa[tx * 8 + n];
                ad[n] = Wa[DIM + tx * 8 + n];
            }
#pragma unroll
            for (int m = 0; m < 4; m++) {
                float ps = 0.f, pd = 0.f;
#pragma unroll
                for (int n = 0; n < 8; n++) {
                    ps = fmaf(acc[m][n], as[n], ps);
                    pd = fmaf(acc[m][n], ad[n], pd);
                }
                sred[0][ty * 4 + m][tx] = ps;
                sred[1][ty * 4 + m][tx] = pd;
            }
            __syncthreads();
            if (tid < 128) {
                int which = tid >> 6;   // 0 = src, 1 = dst
                int r     = tid & 63;
                float s = 0.f;
#pragma unroll
                for (int t = 0; t < 16; t++) s += sred[which][r][t];
                int row = row0 + r;
                if (row < NNODES) {
                    if (which) sdst[row] = s; else ssrc[row] = s;
                }
            }
        }
    }
}

// ---------------------------------------------------------------------------
// Attention kernel: one warp per destination node.
// Edges for node i are contiguous: [i*16, i*16+16).
//   e_j     = s_src[src_j] + s_dst[i] + (W_V * a_t) * edge_d
//   leaky-relu, 16-way softmax (warp shfl), zn = sum_j alpha_j * z[src_j]
//   out = relu(z_i + zn)
// ---------------------------------------------------------------------------
__global__ __launch_bounds__(256) void gat_attn_kernel(
    const int*   __restrict__ edge_src,
    const float* __restrict__ edge_d,
    const float* __restrict__ Wv,    // [1]
    const float* __restrict__ Wa,    // [257]
    const float* __restrict__ z,
    const float* __restrict__ zi,
    const float* __restrict__ ssrc,
    const float* __restrict__ sdst,
    float* __restrict__ out)
{
    const int warp = (blockIdx.x * blockDim.x + threadIdx.x) >> 5;
    const int lane = threadIdx.x & 31;
    if (warp >= NNODES) return;

    const float cE = Wv[0] * Wa[2 * DIM];
    const float sd = sdst[warp];

    int   src = 0;
    float e   = -1e30f;
    if (lane < DEG) {
        src = edge_src[warp * DEG + lane];
        float ev = ssrc[src] + sd + cE * edge_d[warp * DEG + lane];
        e = (ev > 0.f) ? ev : NEG_SLOPE * ev;
    }

    // max over 16 lanes (xor offsets < 16 stay inside the 16-group)
    float m = e;
#pragma unroll
    for (int off = 8; off >= 1; off >>= 1)
        m = fmaxf(m, __shfl_xor_sync(0xffffffffu, m, off));

    float ex = (lane < DEG) ? expf(e - m) : 0.f;
    float s  = ex;
#pragma unroll
    for (int off = 8; off >= 1; off >>= 1)
        s += __shfl_xor_sync(0xffffffffu, s, off);

    const float alpha = ex / s;

    // weighted gather of z rows: lane owns 4 columns
    const int col = lane * 4;
    float4 acc = make_float4(0.f, 0.f, 0.f, 0.f);
#pragma unroll
    for (int j = 0; j < DEG; j++) {
        int   sj = __shfl_sync(0xffffffffu, src,   j);
        float aj = __shfl_sync(0xffffffffu, alpha, j);
        float4 v = *(const float4*)&z[sj * DIM + col];
        acc.x = fmaf(aj, v.x, acc.x);
        acc.y = fmaf(aj, v.y, acc.y);
        acc.z = fmaf(aj, v.z, acc.z);
        acc.w = fmaf(aj, v.w, acc.w);
    }

    float4 zv = *(const float4*)&zi[warp * DIM + col];
    float4 o;
    o.x = fmaxf(zv.x + acc.x, 0.f);
    o.y = fmaxf(zv.y + acc.y, 0.f);
    o.z = fmaxf(zv.z + acc.z, 0.f);
    o.w = fmaxf(zv.w + acc.w, 0.f);
    *(float4*)&out[warp * DIM + col] = o;
}

// ---------------------------------------------------------------------------
// Launch: two GAT layers.
// Input order (metadata): attr, edge_d, W_V1, W_W1, W_U1, W_a1,
//                         W_V2, W_W2, W_U2, W_a2, edge_src, edge_dst
// ---------------------------------------------------------------------------
extern "C" void kernel_launch(void* const* d_in, const int* in_sizes, int n_in,
                              void* d_out, int out_size) {
    const float* attr     = (const float*)d_in[0];
    const float* edge_d   = (const float*)d_in[1];
    const float* W_V1     = (const float*)d_in[2];
    const float* W_W1     = (const float*)d_in[3];
    const float* W_U1     = (const float*)d_in[4];
    const float* W_a1     = (const float*)d_in[5];
    const float* W_V2     = (const float*)d_in[6];
    const float* W_W2     = (const float*)d_in[7];
    const float* W_U2     = (const float*)d_in[8];
    const float* W_a2     = (const float*)d_in[9];
    const int*   edge_src = (const int*)  d_in[10];
    float* out = (float*)d_out;

    static float *zp = nullptr, *zip = nullptr, *hp = nullptr, *ssp = nullptr, *sdp = nullptr;
    if (!zp) {
        cudaGetSymbolAddress((void**)&zp,  g_z);
        cudaGetSymbolAddress((void**)&zip, g_zi);
        cudaGetSymbolAddress((void**)&hp,  g_h);
        cudaGetSymbolAddress((void**)&ssp, g_ss);
        cudaGetSymbolAddress((void**)&sdp, g_sd);
    }

    const int gemm_blocks = (NNODES + 63) / 64;       // 1563
    const int attn_blocks = (NNODES + 7) / 8;         // 12500 (8 warps/block)

    // Layer 1
    gat_gemm_kernel<<<gemm_blocks, 256>>>(attr, W_W1, W_U1, W_a1, zp, zip, ssp, sdp);
    gat_attn_kernel<<<attn_blocks, 256>>>(edge_src, edge_d, W_V1, W_a1,
                                          zp, zip, ssp, sdp, hp);
    // Layer 2
    gat_gemm_kernel<<<gemm_blocks, 256>>>(hp, W_W2, W_U2, W_a2, zp, zip, ssp, sdp);
    gat_attn_kernel<<<attn_blocks, 256>>>(edge_src, edge_d, W_V2, W_a2,
                                          zp, zip, ssp, sdp, out);
}

// round 6
// speedup vs baseline: 2.0999x; 2.0999x over previous
#include <cuda_runtime.h>
#include <cuda_bf16.h>
#include <cstdint>

#define NNODES 100000
#define DEG     16
#define DIM     128
#define NEG_SLOPE 0.01f
#define LDA 136   // bf16 elems per smem row (128 + 8 pad) -> conflict-free ldmatrix

// ---------------- scratch (static device globals; no allocation) ----------------
__device__ float g_z [NNODES * DIM];
__device__ float g_zi[NNODES * DIM];
__device__ float g_h [NNODES * DIM];
__device__ float g_ss[NNODES];
__device__ float g_sd[NNODES];

// ---------------- PTX helpers ----------------
static __device__ __forceinline__ uint32_t sptr(const void* p) {
    return (uint32_t)__cvta_generic_to_shared(p);
}
static __device__ __forceinline__ void ldsm4(uint32_t* r, uint32_t addr) {
    asm volatile("ldmatrix.sync.aligned.m8n8.x4.shared.b16 {%0,%1,%2,%3}, [%4];"
                 : "=r"(r[0]), "=r"(r[1]), "=r"(r[2]), "=r"(r[3]) : "r"(addr));
}
static __device__ __forceinline__ void ldsm4t(uint32_t* r, uint32_t addr) {
    asm volatile("ldmatrix.sync.aligned.m8n8.x4.trans.shared.b16 {%0,%1,%2,%3}, [%4];"
                 : "=r"(r[0]), "=r"(r[1]), "=r"(r[2]), "=r"(r[3]) : "r"(addr));
}
static __device__ __forceinline__ void mma16816(float* c, const uint32_t* a,
                                                uint32_t b0, uint32_t b1) {
    asm volatile(
        "mma.sync.aligned.m16n8k16.row.col.f32.bf16.bf16.f32 "
        "{%0,%1,%2,%3}, {%4,%5,%6,%7}, {%8,%9}, {%0,%1,%2,%3};"
        : "+f"(c[0]), "+f"(c[1]), "+f"(c[2]), "+f"(c[3])
        : "r"(a[0]), "r"(a[1]), "r"(a[2]), "r"(a[3]), "r"(b0), "r"(b1));
}
static __device__ __forceinline__ void split_bf16(float v, __nv_bfloat16& hi, __nv_bfloat16& lo) {
    hi = __float2bfloat16(v);
    lo = __float2bfloat16(v - __bfloat162float(hi));
}

// fill sB[k][n] (hi/lo) from row-major W[n][k]
static __device__ __forceinline__ void fill_w(const float* __restrict__ W,
                                              __nv_bfloat16* sBhi, __nv_bfloat16* sBlo,
                                              int tid) {
#pragma unroll
    for (int p = 0; p < 16; p++) {
        int idx = tid + p * 256;          // 0..4095
        int k4  = idx >> 7;               // 0..31
        int n   = idx & 127;
        float4 v = *(const float4*)&W[n * DIM + k4 * 4];
        float vv[4] = {v.x, v.y, v.z, v.w};
#pragma unroll
        for (int i = 0; i < 4; i++) {
            __nv_bfloat16 hi, lo;
            split_bf16(vv[i], hi, lo);
            int k = k4 * 4 + i;
            sBhi[k * LDA + n] = hi;
            sBlo[k * LDA + n] = lo;
        }
    }
}

// the 3-term bf16 MMA mainloop: C[2][8][4] for a 32x64 warp tile
static __device__ __forceinline__ void mma_mainloop(
    const __nv_bfloat16* sAhi, const __nv_bfloat16* sAlo,
    const __nv_bfloat16* sBhi, const __nv_bfloat16* sBlo,
    float c[2][8][4], int lane, int wm, int wn)
{
#pragma unroll
    for (int mi = 0; mi < 2; mi++)
#pragma unroll
        for (int t = 0; t < 8; t++)
#pragma unroll
            for (int i = 0; i < 4; i++) c[mi][t][i] = 0.f;

    const int arow = lane & 15;
    const int acolh = (lane >> 4) * 8;

#pragma unroll 1
    for (int kb = 0; kb < DIM; kb += 16) {
        uint32_t ahi[2][4], alo[2][4];
#pragma unroll
        for (int mi = 0; mi < 2; mi++) {
            int off = (wm * 32 + mi * 16 + arow) * LDA + kb + acolh;
            ldsm4(ahi[mi], sptr(&sAhi[off]));
            ldsm4(alo[mi], sptr(&sAlo[off]));
        }
        uint32_t bhi[4][4], blo[4][4];
#pragma unroll
        for (int q = 0; q < 4; q++) {
            int off = (kb + arow) * LDA + wn * 64 + q * 16 + acolh;
            ldsm4t(bhi[q], sptr(&sBhi[off]));
            ldsm4t(blo[q], sptr(&sBlo[off]));
        }
#pragma unroll
        for (int mi = 0; mi < 2; mi++)
#pragma unroll
            for (int t = 0; t < 8; t++) {
                int q = t >> 1, hh = (t & 1) * 2;
                mma16816(c[mi][t], ahi[mi], bhi[q][hh], bhi[q][hh + 1]);
                mma16816(c[mi][t], ahi[mi], blo[q][hh], blo[q][hh + 1]);
                mma16816(c[mi][t], alo[mi], bhi[q][hh], bhi[q][hh + 1]);
            }
    }
}

// ---------------------------------------------------------------------------
// GEMM: per 128-row tile, z = h@Ww^T (+ fused s_src/s_dst), zi = h@Wu^T
// ---------------------------------------------------------------------------
__global__ __launch_bounds__(256) void gat_gemm_kernel(
    const float* __restrict__ h,
    const float* __restrict__ Ww,
    const float* __restrict__ Wu,
    const float* __restrict__ Wa,
    float* __restrict__ z,
    float* __restrict__ zi,
    float* __restrict__ ssrc,
    float* __restrict__ sdst)
{
    extern __shared__ __align__(16) char smem_raw[];
    __nv_bfloat16* sAhi = (__nv_bfloat16*)smem_raw;
    __nv_bfloat16* sAlo = sAhi + 128 * LDA;
    __nv_bfloat16* sBhi = sAlo + 128 * LDA;
    __nv_bfloat16* sBlo = sBhi + 128 * LDA;
    float*         sred = (float*)(sBlo + 128 * LDA);  // [256]: 0..127 src, 128..255 dst

    const int tid  = threadIdx.x;
    const int lane = tid & 31;
    const int warp = tid >> 5;
    const int wm   = warp & 3;     // 0..3 -> 32-row strip
    const int wn   = warp >> 2;    // 0..1 -> 64-col strip
    const int row0 = blockIdx.x * 128;

    sred[tid] = 0.f;

    // ---- stage A tile (fp32 -> bf16 hi/lo) ----
#pragma unroll
    for (int p = 0; p < 16; p++) {
        int idx = tid + p * 256;
        int r   = idx >> 5;
        int c4  = idx & 31;
        float4 v = make_float4(0.f, 0.f, 0.f, 0.f);
        int row = row0 + r;
        if (row < NNODES) v = *(const float4*)&h[row * DIM + c4 * 4];
        float vv[4] = {v.x, v.y, v.z, v.w};
        __nv_bfloat16 hi[4], lo[4];
#pragma unroll
        for (int i = 0; i < 4; i++) split_bf16(vv[i], hi[i], lo[i]);
        __nv_bfloat162* ph = (__nv_bfloat162*)&sAhi[r * LDA + c4 * 4];
        __nv_bfloat162* pl = (__nv_bfloat162*)&sAlo[r * LDA + c4 * 4];
        ph[0] = __halves2bfloat162(hi[0], hi[1]);
        ph[1] = __halves2bfloat162(hi[2], hi[3]);
        pl[0] = __halves2bfloat162(lo[0], lo[1]);
        pl[1] = __halves2bfloat162(lo[2], lo[3]);
    }
    fill_w(Ww, sBhi, sBlo, tid);
    __syncthreads();

    float c[2][8][4];

    // ================= matrix 1: z = h @ Ww^T =================
    mma_mainloop(sAhi, sAlo, sBhi, sBlo, c, lane, wm, wn);

    // write z + s partials
#pragma unroll
    for (int mi = 0; mi < 2; mi++) {
        float ps[2] = {0.f, 0.f}, pd[2] = {0.f, 0.f};
#pragma unroll
        for (int t = 0; t < 8; t++) {
            int col = wn * 64 + t * 8 + (lane & 3) * 2;
            float as0 = Wa[col], as1 = Wa[col + 1];
            float ad0 = Wa[DIM + col], ad1 = Wa[DIM + col + 1];
#pragma unroll
            for (int hh = 0; hh < 2; hh++) {
                int row = row0 + wm * 32 + mi * 16 + hh * 8 + (lane >> 2);
                if (row < NNODES)
                    *(float2*)&z[row * DIM + col] =
                        make_float2(c[mi][t][hh * 2], c[mi][t][hh * 2 + 1]);
                ps[hh] = fmaf(c[mi][t][hh * 2], as0, fmaf(c[mi][t][hh * 2 + 1], as1, ps[hh]));
                pd[hh] = fmaf(c[mi][t][hh * 2], ad0, fmaf(c[mi][t][hh * 2 + 1], ad1, pd[hh]));
            }
        }
#pragma unroll
        for (int hh = 0; hh < 2; hh++) {
            int lr = wm * 32 + mi * 16 + hh * 8 + (lane >> 2);
            atomicAdd(&sred[lr], ps[hh]);
            atomicAdd(&sred[128 + lr], pd[hh]);
        }
    }
    __syncthreads();

    // flush s_src / s_dst, then refill B with Wu
    {
        int which = tid >> 7;           // 0 = src, 1 = dst
        int r     = tid & 127;
        int row   = row0 + r;
        if (row < NNODES) {
            float s = sred[which * 128 + r];
            if (which) sdst[row] = s; else ssrc[row] = s;
        }
    }
    fill_w(Wu, sBhi, sBlo, tid);
    __syncthreads();

    // ================= matrix 2: zi = h @ Wu^T =================
    mma_mainloop(sAhi, sAlo, sBhi, sBlo, c, lane, wm, wn);

#pragma unroll
    for (int mi = 0; mi < 2; mi++)
#pragma unroll
        for (int t = 0; t < 8; t++) {
            int col = wn * 64 + t * 8 + (lane & 3) * 2;
#pragma unroll
            for (int hh = 0; hh < 2; hh++) {
                int row = row0 + wm * 32 + mi * 16 + hh * 8 + (lane >> 2);
                if (row < NNODES)
                    *(float2*)&zi[row * DIM + col] =
                        make_float2(c[mi][t][hh * 2], c[mi][t][hh * 2 + 1]);
            }
        }
}

// ---------------------------------------------------------------------------
// Attention kernel: one warp per destination node (unchanged, known-good)
// ---------------------------------------------------------------------------
__global__ __launch_bounds__(256) void gat_attn_kernel(
    const int*   __restrict__ edge_src,
    const float* __restrict__ edge_d,
    const float* __restrict__ Wv,
    const float* __restrict__ Wa,
    const float* __restrict__ z,
    const float* __restrict__ zi,
    const float* __restrict__ ssrc,
    const float* __restrict__ sdst,
    float* __restrict__ out)
{
    const int warp = (blockIdx.x * blockDim.x + threadIdx.x) >> 5;
    const int lane = threadIdx.x & 31;
    if (warp >= NNODES) return;

    const float cE = Wv[0] * Wa[2 * DIM];
    const float sd = sdst[warp];

    int   src = 0;
    float e   = -1e30f;
    if (lane < DEG) {
        src = edge_src[warp * DEG + lane];
        float ev = ssrc[src] + sd + cE * edge_d[warp * DEG + lane];
        e = (ev > 0.f) ? ev : NEG_SLOPE * ev;
    }

    float m = e;
#pragma unroll
    for (int off = 8; off >= 1; off >>= 1)
        m = fmaxf(m, __shfl_xor_sync(0xffffffffu, m, off));

    float ex = (lane < DEG) ? expf(e - m) : 0.f;
    float s  = ex;
#pragma unroll
    for (int off = 8; off >= 1; off >>= 1)
        s += __shfl_xor_sync(0xffffffffu, s, off);

    const float alpha = ex / s;

    const int col = lane * 4;
    float4 acc = make_float4(0.f, 0.f, 0.f, 0.f);
#pragma unroll
    for (int j = 0; j < DEG; j++) {
        int   sj = __shfl_sync(0xffffffffu, src,   j);
        float aj = __shfl_sync(0xffffffffu, alpha, j);
        float4 v = *(const float4*)&z[sj * DIM + col];
        acc.x = fmaf(aj, v.x, acc.x);
        acc.y = fmaf(aj, v.y, acc.y);
        acc.z = fmaf(aj, v.z, acc.z);
        acc.w = fmaf(aj, v.w, acc.w);
    }

    float4 zv = *(const float4*)&zi[warp * DIM + col];
    float4 o;
    o.x = fmaxf(zv.x + acc.x, 0.f);
    o.y = fmaxf(zv.y + acc.y, 0.f);
    o.z = fmaxf(zv.z + acc.z, 0.f);
    o.w = fmaxf(zv.w + acc.w, 0.f);
    *(float4*)&out[warp * DIM + col] = o;
}

// ---------------------------------------------------------------------------
extern "C" void kernel_launch(void* const* d_in, const int* in_sizes, int n_in,
                              void* d_out, int out_size) {
    const float* attr     = (const float*)d_in[0];
    const float* edge_d   = (const float*)d_in[1];
    const float* W_V1     = (const float*)d_in[2];
    const float* W_W1     = (const float*)d_in[3];
    const float* W_U1     = (const float*)d_in[4];
    const float* W_a1     = (const float*)d_in[5];
    const float* W_V2     = (const float*)d_in[6];
    const float* W_W2     = (const float*)d_in[7];
    const float* W_U2     = (const float*)d_in[8];
    const float* W_a2     = (const float*)d_in[9];
    const int*   edge_src = (const int*)  d_in[10];
    float* out = (float*)d_out;

    static float *zp = nullptr, *zip = nullptr, *hp = nullptr, *ssp = nullptr, *sdp = nullptr;
    static int smem_bytes = 0;
    if (!zp) {
        cudaGetSymbolAddress((void**)&zp,  g_z);
        cudaGetSymbolAddress((void**)&zip, g_zi);
        cudaGetSymbolAddress((void**)&hp,  g_h);
        cudaGetSymbolAddress((void**)&ssp, g_ss);
        cudaGetSymbolAddress((void**)&sdp, g_sd);
        smem_bytes = 4 * 128 * LDA * (int)sizeof(__nv_bfloat16) + 256 * (int)sizeof(float);
        cudaFuncSetAttribute(gat_gemm_kernel,
                             cudaFuncAttributeMaxDynamicSharedMemorySize, smem_bytes);
    }

    const int gemm_blocks = (NNODES + 127) / 128;     // 782
    const int attn_blocks = (NNODES + 7) / 8;         // 12500

    // Layer 1
    gat_gemm_kernel<<<gemm_blocks, 256, smem_bytes>>>(attr, W_W1, W_U1, W_a1, zp, zip, ssp, sdp);
    gat_attn_kernel<<<attn_blocks, 256>>>(edge_src, edge_d, W_V1, W_a1,
                                          zp, zip, ssp, sdp, hp);
    // Layer 2
    gat_gemm_kernel<<<gemm_blocks, 256, smem_bytes>>>(hp, W_W2, W_U2, W_a2, zp, zip, ssp, sdp);
    gat_attn_kernel<<<attn_blocks, 256>>>(edge_src, edge_d, W_V2, W_a2,
                                          zp, zip, ssp, sdp, out);
}